// round 6
// baseline (speedup 1.0000x reference)
#include <cuda_runtime.h>

#define B_      16
#define D_      64
#define N_      256
#define E_      64
#define HID_    128
#define OUT_    64
#define IN_     192
#define R_PAIRS 32640
#define NB      384      // persistent blocks; 3/SM guaranteed by launch_bounds
#define NTH     256
#define XS_PAD  68
#define US_PAD  18

// Scratch. U,V layout: [b][n][h]
__device__ float g_U[B_ * N_ * HID_];
__device__ float g_V[B_ * N_ * HID_];
__device__ float g_C[B_ * HID_];
__device__ float g_LinPart[B_ * HID_ * 8];
__device__ float g_SabsPart[B_ * 32 * 3 * HID_];   // [b][tile][jthird][h]
__device__ unsigned g_barCnt = 0;
__device__ volatile unsigned g_barGen = 0;

// ---------------- packed f32x2 helpers ----------------
__device__ __forceinline__ void fma2(unsigned long long& acc,
                                     unsigned long long w, unsigned long long x) {
    asm("fma.rn.f32x2 %0, %1, %2, %3;" : "=l"(acc) : "l"(w), "l"(x), "l"(acc));
}
__device__ __forceinline__ unsigned long long pack2(float a, float b) {
    unsigned long long r;
    asm("mov.b64 %0, {%1, %2};" : "=l"(r) : "f"(a), "f"(b));
    return r;
}
__device__ __forceinline__ float lo2(unsigned long long v) {
    return __uint_as_float((unsigned)(v & 0xffffffffu));
}
__device__ __forceinline__ float hi2(unsigned long long v) {
    return __uint_as_float((unsigned)(v >> 32));
}
__device__ __forceinline__ void add2(unsigned long long& acc, unsigned long long x) {
    asm("add.rn.f32x2 %0, %1, %2;" : "=l"(acc) : "l"(acc), "l"(x));
}
__device__ __forceinline__ void addabs2(unsigned long long& acc,
                                        unsigned long long t2, unsigned long long v2,
                                        unsigned long long mask) {
    unsigned long long x;
    asm("add.rn.f32x2 %0, %1, %2;" : "=l"(x) : "l"(t2), "l"(v2));
    asm("and.b64 %0, %1, %2;" : "=l"(x) : "l"(x), "l"(mask));
    asm("add.rn.f32x2 %0, %1, %2;" : "=l"(acc) : "l"(acc), "l"(x));
}

// ---------------- device-wide barrier (all NB blocks resident) ----------------
__device__ __forceinline__ void grid_barrier() {
    __syncthreads();
    if (threadIdx.x == 0) {
        unsigned gen = g_barGen;
        __threadfence();
        if (atomicAdd(&g_barCnt, 1u) == NB - 1) {
            g_barCnt = 0;
            __threadfence();
            g_barGen = gen + 1;
        } else {
            while (g_barGen == gen) { __nanosleep(16); }
        }
        __threadfence();
    }
    __syncthreads();
}

// ---------------------------------------------------------------------------
__global__ __launch_bounds__(NTH, 3) void fused_kernel(
    const float* __restrict__ x, const float* __restrict__ emb,
    const float* __restrict__ W1, const float* __restrict__ b1,
    const float* __restrict__ W2, const float* __restrict__ b2,
    float* __restrict__ out)
{
    __shared__ __align__(16) float xs[32 * XS_PAD];
    __shared__ __align__(16) float us[32 * US_PAD];
    __shared__ __align__(16) float vs[32 * US_PAD];
    __shared__ float Ss[HID_];
    const int blk  = blockIdx.x;
    const int tid  = threadIdx.x;
    const int w    = tid >> 5;
    const int lane = tid & 31;

    // ---- c[b][h] = b1[h] + W1[h,128:192].emb[b]  (blocks 0..15) ----
    if (blk < B_ && tid < HID_) {
        int b = blk, h = tid;
        const float4* wr = (const float4*)(W1 + h * IN_ + 2 * D_);
        const float4* er = (const float4*)(emb + b * E_);
        float acc = b1[h];
#pragma unroll
        for (int e4 = 0; e4 < E_ / 4; ++e4) {
            float4 ww = wr[e4]; float4 ee = er[e4];
            acc += ww.x * ee.x + ww.y * ee.y + ww.z * ee.z + ww.w * ee.w;
        }
        g_C[b * HID_ + h] = acc;
    }

    // ================= Phase 1: U,V (transposed store) + lin partials ========
    // 1024 units = b(16) x hgroup(8) x ntile(8); strided over NB blocks.
#pragma unroll 1
    for (int s = 0; s < 3; ++s) {
        int u = blk + s * NB;
        if (u >= 1024) break;
        int b  = u >> 6;
        int hg = (u >> 3) & 7;
        int nt = u & 7;
        int n0 = nt * 32;

        __syncthreads();
        {
            const float4* xg = (const float4*)(x + b * D_ * N_ + n0);
#pragma unroll
            for (int t = tid; t < 512; t += NTH) {
                int d  = t >> 3;
                int c4 = t & 7;
                float4 vv = xg[d * (N_ / 4) + c4];
                int nl = c4 * 4;
                xs[(nl + 0) * XS_PAD + d] = vv.x;
                xs[(nl + 1) * XS_PAD + d] = vv.y;
                xs[(nl + 2) * XS_PAD + d] = vv.z;
                xs[(nl + 3) * XS_PAD + d] = vv.w;
            }
        }
        __syncthreads();

        int h1 = hg * 16 + w;
        int h2 = h1 + 8;
        const ulonglong2* wa1 = (const ulonglong2*)(W1 + h1 * IN_);
        const ulonglong2* wb1 = (const ulonglong2*)(W1 + h1 * IN_ + D_);
        const ulonglong2* wa2 = (const ulonglong2*)(W1 + h2 * IN_);
        const ulonglong2* wb2 = (const ulonglong2*)(W1 + h2 * IN_ + D_);
        const ulonglong2* xr  = (const ulonglong2*)(xs + lane * XS_PAD);

        unsigned long long au1 = 0ull, av1 = 0ull, au2 = 0ull, av2 = 0ull;
#pragma unroll 8
        for (int d4 = 0; d4 < 16; ++d4) {
            ulonglong2 xv = xr[d4];
            ulonglong2 A1 = wa1[d4], B1 = wb1[d4];
            ulonglong2 A2 = wa2[d4], B2 = wb2[d4];
            fma2(au1, A1.x, xv.x); fma2(au1, A1.y, xv.y);
            fma2(av1, B1.x, xv.x); fma2(av1, B1.y, xv.y);
            fma2(au2, A2.x, xv.x); fma2(au2, A2.y, xv.y);
            fma2(av2, B2.x, xv.x); fma2(av2, B2.y, xv.y);
        }
        float u1 = lo2(au1) + hi2(au1), v1 = lo2(av1) + hi2(av1);
        float u2 = lo2(au2) + hi2(au2), v2 = lo2(av2) + hi2(av2);

        float nf = (float)(n0 + lane);
        float l1 = u1 * (255.0f - nf) + v1 * nf;
        float l2 = u2 * (255.0f - nf) + v2 * nf;
#pragma unroll
        for (int o = 16; o; o >>= 1) {
            l1 += __shfl_xor_sync(0xffffffffu, l1, o);
            l2 += __shfl_xor_sync(0xffffffffu, l2, o);
        }
        if (lane == 0) {
            g_LinPart[(b * HID_ + h1) * 8 + nt] = l1;
            g_LinPart[(b * HID_ + h2) * 8 + nt] = l2;
        }

        us[lane * US_PAD + w]     = u1;
        us[lane * US_PAD + w + 8] = u2;
        vs[lane * US_PAD + w]     = v1;
        vs[lane * US_PAD + w + 8] = v2;
        __syncthreads();

        {
            int n  = tid >> 3;
            int hp = tid & 7;
            float2 uu = *(const float2*)(us + n * US_PAD + 2 * hp);
            float2 vv = *(const float2*)(vs + n * US_PAD + 2 * hp);
            int row = b * N_ + n0 + n;
            ((float2*)g_U)[row * (HID_ / 2) + hg * 8 + hp] = uu;
            ((float2*)g_V)[row * (HID_ / 2) + hg * 8 + hp] = vv;
        }
    }

    grid_barrier();

    // ================= Phase 2: Sabs partials ================================
    // 384 units = (b, pg in 0..7, jthird). Block: 4 tiles {2pg,2pg+1,31-2pg,30-2pg},
    // warp -> (tile, hp-half); each block covers third jt of each tile's j-range.
    {
        const unsigned long long mask = 0x7FFFFFFF7FFFFFFFull;
        int jt = blk % 3;
        int pg = (blk / 3) & 7;
        int b  = blk / 24;
        int ti = (w < 4) ? w : ((w + 2) & 3);
        int hp = ((w < 4) ? 0 : 32) + lane;
        int tile = (ti == 0) ? 2 * pg
                 : (ti == 1) ? 2 * pg + 1
                 : (ti == 2) ? 31 - 2 * pg
                 :             30 - 2 * pg;
        int i0   = tile * 8;
        int jbeg = i0 + 8;
        int len  = N_ - jbeg;                 // multiple of 8 (0 for tile 31)
        int q    = (len / 3) & ~3;            // per-third, multiple of 4
        int jlo  = jbeg + jt * q;
        int jhi  = (jt == 2) ? N_ : (jlo + q);

        const float2* U2 = (const float2*)g_U + (size_t)b * N_ * (HID_ / 2) + hp;
        const unsigned long long* V2 =
            (const unsigned long long*)g_V + (size_t)b * N_ * (HID_ / 2) + hp;
        float2 cc = ((const float2*)g_C)[b * (HID_ / 2) + hp];

        unsigned long long t2[8], a2[8];
#pragma unroll
        for (int k = 0; k < 8; ++k) {
            float2 uu = U2[(i0 + k) * (HID_ / 2)];
            t2[k] = pack2(uu.x + cc.x, uu.y + cc.y);
            a2[k] = 0ull;
        }

        // triangular corner: only jthird 0
        if (jt == 0) {
#pragma unroll
            for (int jj = 1; jj < 8; ++jj) {
                unsigned long long v2 = V2[(i0 + jj) * (HID_ / 2)];
#pragma unroll
                for (int k = 0; k < jj; ++k) addabs2(a2[k], t2[k], v2, mask);
            }
        }

        // main: 8 j per iteration (8 outstanding LDG.64), then 4-j remainder
        int j = jlo;
        for (; j + 8 <= jhi; j += 8) {
            unsigned long long p0 = V2[(j + 0) * (HID_ / 2)];
            unsigned long long p1 = V2[(j + 1) * (HID_ / 2)];
            unsigned long long p2 = V2[(j + 2) * (HID_ / 2)];
            unsigned long long p3 = V2[(j + 3) * (HID_ / 2)];
            unsigned long long p4 = V2[(j + 4) * (HID_ / 2)];
            unsigned long long p5 = V2[(j + 5) * (HID_ / 2)];
            unsigned long long p6 = V2[(j + 6) * (HID_ / 2)];
            unsigned long long p7 = V2[(j + 7) * (HID_ / 2)];
#pragma unroll
            for (int k = 0; k < 8; ++k) {
                addabs2(a2[k], t2[k], p0, mask);
                addabs2(a2[k], t2[k], p1, mask);
                addabs2(a2[k], t2[k], p2, mask);
                addabs2(a2[k], t2[k], p3, mask);
                addabs2(a2[k], t2[k], p4, mask);
                addabs2(a2[k], t2[k], p5, mask);
                addabs2(a2[k], t2[k], p6, mask);
                addabs2(a2[k], t2[k], p7, mask);
            }
        }
        for (; j < jhi; j += 4) {
            unsigned long long p0 = V2[(j + 0) * (HID_ / 2)];
            unsigned long long p1 = V2[(j + 1) * (HID_ / 2)];
            unsigned long long p2 = V2[(j + 2) * (HID_ / 2)];
            unsigned long long p3 = V2[(j + 3) * (HID_ / 2)];
#pragma unroll
            for (int k = 0; k < 8; ++k) {
                addabs2(a2[k], t2[k], p0, mask);
                addabs2(a2[k], t2[k], p1, mask);
                addabs2(a2[k], t2[k], p2, mask);
                addabs2(a2[k], t2[k], p3, mask);
            }
        }

        unsigned long long s2 = a2[0];
        add2(s2, a2[1]); add2(s2, a2[2]); add2(s2, a2[3]);
        add2(s2, a2[4]); add2(s2, a2[5]); add2(s2, a2[6]); add2(s2, a2[7]);
        float2 res = {lo2(s2), hi2(s2)};
        ((float2*)g_SabsPart)[((b * 32 + tile) * 3 + jt) * (HID_ / 2) + hp] = res;
    }

    grid_barrier();

    // ================= Phase 3: reduce + output GEMM (blocks 0..15) ==========
    if (blk < B_) {
        int b = blk;
        if (tid < HID_) {
            int hh = tid;
            float lin = 0.0f;
#pragma unroll
            for (int q2 = 0; q2 < 8; ++q2) lin += g_LinPart[(b * HID_ + hh) * 8 + q2];
            float sab = 0.0f;
#pragma unroll
            for (int t = 0; t < 96; ++t)
                sab += g_SabsPart[(b * 96 + t) * HID_ + hh];
            lin += g_C[b * HID_ + hh] * (float)R_PAIRS;
            Ss[hh] = 0.5f * (lin + sab);
        }
        __syncthreads();
        if (tid < OUT_) {
            int o = tid;
            const float4* wv = (const float4*)(W2 + o * HID_);
            const float4* sv = (const float4*)Ss;
            float acc = 0.0f;
#pragma unroll
            for (int q2 = 0; q2 < HID_ / 4; ++q2) {
                float4 ww = wv[q2]; float4 ssv = sv[q2];
                acc += ww.x * ssv.x + ww.y * ssv.y + ww.z * ssv.z + ww.w * ssv.w;
            }
            out[b * OUT_ + o] = acc + (float)R_PAIRS * b2[o];
        }
    }
}

// ---------------------------------------------------------------------------
extern "C" void kernel_launch(void* const* d_in, const int* in_sizes, int n_in,
                              void* d_out, int out_size) {
    const float* x   = (const float*)d_in[0];
    const float* emb = (const float*)d_in[1];
    const float* W1  = (const float*)d_in[2];
    const float* b1  = (const float*)d_in[3];
    const float* W2  = (const float*)d_in[4];
    const float* b2  = (const float*)d_in[5];
    float* out = (float*)d_out;

    fused_kernel<<<NB, NTH>>>(x, emb, W1, b1, W2, b2, out);
}

// round 7
// speedup vs baseline: 1.0147x; 1.0147x over previous
#include <cuda_runtime.h>

#define B_      16
#define D_      64
#define N_      256
#define E_      64
#define HID_    128
#define OUT_    64
#define IN_     192
#define R_PAIRS 32640
#define XS_PAD  68
#define US_PAD  18

// Scratch. U,V layout: [b][n][h] (h contiguous)
__device__ float g_U[B_ * N_ * HID_];
__device__ float g_V[B_ * N_ * HID_];
__device__ float g_C[B_ * HID_];
__device__ float g_LinPart[B_ * HID_ * 8];        // [(b*HID+h)*8 + ntile]
__device__ float g_SabsPart[B_ * 64 * HID_];      // [(b*64 + tp*4+jq)*HID + h]

// ---------------- packed f32x2 helpers ----------------
__device__ __forceinline__ void fma2(unsigned long long& acc,
                                     unsigned long long w, unsigned long long x) {
    asm("fma.rn.f32x2 %0, %1, %2, %3;" : "=l"(acc) : "l"(w), "l"(x), "l"(acc));
}
__device__ __forceinline__ unsigned long long pack2(float a, float b) {
    unsigned long long r;
    asm("mov.b64 %0, {%1, %2};" : "=l"(r) : "f"(a), "f"(b));
    return r;
}
__device__ __forceinline__ float lo2(unsigned long long v) {
    return __uint_as_float((unsigned)(v & 0xffffffffu));
}
__device__ __forceinline__ float hi2(unsigned long long v) {
    return __uint_as_float((unsigned)(v >> 32));
}
__device__ __forceinline__ void addabs2(unsigned long long& acc,
                                        unsigned long long t2, unsigned long long v2,
                                        unsigned long long mask) {
    unsigned long long x;
    asm("add.rn.f32x2 %0, %1, %2;" : "=l"(x) : "l"(t2), "l"(v2));
    asm("and.b64 %0, %1, %2;" : "=l"(x) : "l"(x), "l"(mask));
    asm("add.rn.f32x2 %0, %1, %2;" : "=l"(acc) : "l"(acc), "l"(x));
}

// ===========================================================================
// Kernel 1: U,V (transposed), C, lin partials.
// grid = 1024 = (b:16, hg:8, nt:8); block = 256.
// ===========================================================================
__global__ __launch_bounds__(256, 4) void uv_kernel(
    const float* __restrict__ x, const float* __restrict__ emb,
    const float* __restrict__ W1, const float* __restrict__ b1)
{
    __shared__ __align__(16) float xs[32 * XS_PAD];
    __shared__ __align__(16) float us[32 * US_PAD];
    __shared__ __align__(16) float vs[32 * US_PAD];
    const int bx   = blockIdx.x;
    const int nt   = bx & 7;
    const int hg   = (bx >> 3) & 7;
    const int b    = bx >> 6;
    const int tid  = threadIdx.x;
    const int w    = tid >> 5;
    const int lane = tid & 31;
    const int n0   = nt * 32;

    // C[b][h] for this hg (one block per (b,hg) does it: nt==7)
    if (nt == 7 && tid < 16) {
        int h = hg * 16 + tid;
        const float4* wr = (const float4*)(W1 + h * IN_ + 2 * D_);
        const float4* er = (const float4*)(emb + b * E_);
        float acc = b1[h];
#pragma unroll
        for (int e4 = 0; e4 < E_ / 4; ++e4) {
            float4 ww = wr[e4]; float4 ee = er[e4];
            acc += ww.x * ee.x + ww.y * ee.y + ww.z * ee.z + ww.w * ee.w;
        }
        g_C[b * HID_ + h] = acc;
    }

    // stage x[b][0:64][n0:n0+32] transposed into xs[n][d]
    {
        const float4* xg = (const float4*)(x + b * D_ * N_ + n0);
#pragma unroll
        for (int t = tid; t < 512; t += 256) {
            int d  = t >> 3;
            int c4 = t & 7;
            float4 vv = xg[d * (N_ / 4) + c4];
            int nl = c4 * 4;
            xs[(nl + 0) * XS_PAD + d] = vv.x;
            xs[(nl + 1) * XS_PAD + d] = vv.y;
            xs[(nl + 2) * XS_PAD + d] = vv.z;
            xs[(nl + 3) * XS_PAD + d] = vv.w;
        }
    }
    __syncthreads();

    int h1 = hg * 16 + w;
    int h2 = h1 + 8;
    const ulonglong2* wa1 = (const ulonglong2*)(W1 + h1 * IN_);
    const ulonglong2* wb1 = (const ulonglong2*)(W1 + h1 * IN_ + D_);
    const ulonglong2* wa2 = (const ulonglong2*)(W1 + h2 * IN_);
    const ulonglong2* wb2 = (const ulonglong2*)(W1 + h2 * IN_ + D_);
    const ulonglong2* xr  = (const ulonglong2*)(xs + lane * XS_PAD);

    unsigned long long au1 = 0ull, av1 = 0ull, au2 = 0ull, av2 = 0ull;
#pragma unroll 8
    for (int d4 = 0; d4 < 16; ++d4) {
        ulonglong2 xv = xr[d4];
        ulonglong2 A1 = wa1[d4], B1 = wb1[d4];
        ulonglong2 A2 = wa2[d4], B2 = wb2[d4];
        fma2(au1, A1.x, xv.x); fma2(au1, A1.y, xv.y);
        fma2(av1, B1.x, xv.x); fma2(av1, B1.y, xv.y);
        fma2(au2, A2.x, xv.x); fma2(au2, A2.y, xv.y);
        fma2(av2, B2.x, xv.x); fma2(av2, B2.y, xv.y);
    }
    float u1 = lo2(au1) + hi2(au1), v1 = lo2(av1) + hi2(av1);
    float u2 = lo2(au2) + hi2(au2), v2 = lo2(av2) + hi2(av2);

    // lin partials
    float nf = (float)(n0 + lane);
    float l1 = u1 * (255.0f - nf) + v1 * nf;
    float l2 = u2 * (255.0f - nf) + v2 * nf;
#pragma unroll
    for (int o = 16; o; o >>= 1) {
        l1 += __shfl_xor_sync(0xffffffffu, l1, o);
        l2 += __shfl_xor_sync(0xffffffffu, l2, o);
    }
    if (lane == 0) {
        g_LinPart[(b * HID_ + h1) * 8 + nt] = l1;
        g_LinPart[(b * HID_ + h2) * 8 + nt] = l2;
    }

    // transpose via smem -> coalesced STG.64 in [b][n][h] layout
    us[lane * US_PAD + w]     = u1;
    us[lane * US_PAD + w + 8] = u2;
    vs[lane * US_PAD + w]     = v1;
    vs[lane * US_PAD + w + 8] = v2;
    __syncthreads();
    {
        int n  = tid >> 3;
        int hp = tid & 7;
        float2 uu = *(const float2*)(us + n * US_PAD + 2 * hp);
        float2 vv = *(const float2*)(vs + n * US_PAD + 2 * hp);
        int row = b * N_ + n0 + n;
        ((float2*)g_U)[row * (HID_ / 2) + hg * 8 + hp] = uu;
        ((float2*)g_V)[row * (HID_ / 2) + hg * 8 + hp] = vv;
    }
}

// ===========================================================================
// Kernel 2: Sabs partials.
// grid = 1024 = (b:16, tp:16, jq:4); block = 256 (8 warps).
// Block handles tiles {tp, 31-tp} (exactly 248 j-cols total -> equal blocks).
// warp w: tile_sel = w&1, hhalf = (w>>1)&1, jhalf = w>>2.
// j-range of a tile split into 8 even pieces (jq*2 + jhalf); piece 0 + corner.
// In-block smem reduce -> 1 partial per (b,tp,jq,h).
// ===========================================================================
__global__ __launch_bounds__(256, 4) void pair_kernel()
{
    __shared__ float2 red[8][64];
    const unsigned long long mask = 0x7FFFFFFF7FFFFFFFull;
    const int bx   = blockIdx.x;
    const int jq   = bx & 3;
    const int tp   = (bx >> 2) & 15;
    const int b    = bx >> 6;
    const int tid  = threadIdx.x;
    const int w    = tid >> 5;
    const int lane = tid & 31;

    const int ts   = w & 1;
    const int hh   = (w >> 1) & 1;
    const int jh   = w >> 2;
    const int tile = ts ? (31 - tp) : tp;
    const int hp   = hh * 32 + lane;          // float2 (h-pair) index 0..63

    const int i0   = tile * 8;
    const int jbeg = i0 + 8;
    const int len  = N_ - jbeg;               // 248 - 8*tile, multiple of 8
    const int q    = len >> 3;                // per-piece count (exact)
    const int pi   = jq * 2 + jh;             // piece 0..7
    const int jlo  = jbeg + pi * q;
    const int jhi  = jlo + q;

    const float2* U2 = (const float2*)g_U + (size_t)b * N_ * (HID_ / 2) + hp;
    const unsigned long long* V2 =
        (const unsigned long long*)g_V + (size_t)b * N_ * (HID_ / 2) + hp;
    float2 cc = ((const float2*)g_C)[b * (HID_ / 2) + hp];

    unsigned long long t2[8], a2[8];
#pragma unroll
    for (int k = 0; k < 8; ++k) {
        float2 uu = U2[(i0 + k) * (HID_ / 2)];
        t2[k] = pack2(uu.x + cc.x, uu.y + cc.y);
        a2[k] = 0ull;
    }

    // triangular corner: piece 0 only
    if (pi == 0) {
#pragma unroll
        for (int jj = 1; jj < 8; ++jj) {
            unsigned long long v2 = V2[(i0 + jj) * (HID_ / 2)];
#pragma unroll
            for (int k = 0; k < jj; ++k) addabs2(a2[k], t2[k], v2, mask);
        }
    }

    // main loop: 4 j / iteration, scalar tail (q may be odd)
    int j = jlo;
    for (; j + 4 <= jhi; j += 4) {
        unsigned long long p0 = V2[(j + 0) * (HID_ / 2)];
        unsigned long long p1 = V2[(j + 1) * (HID_ / 2)];
        unsigned long long p2 = V2[(j + 2) * (HID_ / 2)];
        unsigned long long p3 = V2[(j + 3) * (HID_ / 2)];
#pragma unroll
        for (int k = 0; k < 8; ++k) {
            addabs2(a2[k], t2[k], p0, mask);
            addabs2(a2[k], t2[k], p1, mask);
            addabs2(a2[k], t2[k], p2, mask);
            addabs2(a2[k], t2[k], p3, mask);
        }
    }
    for (; j < jhi; ++j) {
        unsigned long long p0 = V2[j * (HID_ / 2)];
#pragma unroll
        for (int k = 0; k < 8; ++k) addabs2(a2[k], t2[k], p0, mask);
    }

    // per-warp packed sum
    unsigned long long s2 = a2[0];
#pragma unroll
    for (int k = 1; k < 8; ++k)
        asm("add.rn.f32x2 %0, %1, %2;" : "=l"(s2) : "l"(s2), "l"(a2[k]));
    red[w][lane] = make_float2(lo2(s2), hi2(s2));
    __syncthreads();

    // combine the 4 warps sharing each hhalf; one store per (hp)
    if (tid < 128) {
        int hh2 = tid >> 6;
        int idx = tid & 63;
        int base = hh2 * 2;            // warps {2hh, 2hh+1, 2hh+4, 2hh+5}
        float2 r0 = red[base + 0][idx & 31];
        // careful: red indexed [warp][lane]; idx 0..63 spans both tile_sel warps’ lanes?
        // No: each warp covers hp = hh*32 + lane, so within an hhalf the two
        // tile_sel warps and two jhalf warps all cover the SAME 32 hp values.
        // idx should be 0..31 only per hhalf -> use 64 threads per hhalf over hp pairs:
        r0 = red[base + 0][idx];       // placeholder; fixed below
        (void)r0;
    }
    // -- corrected reduction: 64 threads, each owns one hp of one hhalf --
    if (tid < 128) {
        int hh2 = tid >> 6;            // hhalf
        int l   = tid & 63;
        if (l < 32) {
            int base = hh2 * 2;
            float2 A = red[base + 0][l];
            float2 Bv = red[base + 1][l];
            float2 Cv = red[base + 4][l];
            float2 Dv = red[base + 5][l];
            float2 r;
            r.x = (A.x + Bv.x) + (Cv.x + Dv.x);
            r.y = (A.y + Bv.y) + (Cv.y + Dv.y);
            int slot = b * 64 + tp * 4 + jq;
            ((float2*)g_SabsPart)[slot * (HID_ / 2) + hh2 * 32 + l] = r;
        }
    }
}

// ===========================================================================
// Kernel 3: reduce partials + output GEMM. grid = 16, block = 128.
// ===========================================================================
__global__ __launch_bounds__(128) void out_kernel(
    const float* __restrict__ W2, const float* __restrict__ b2,
    float* __restrict__ out)
{
    __shared__ float Ss[HID_];
    const int b   = blockIdx.x;
    const int h   = threadIdx.x;

    float sab = 0.0f;
#pragma unroll 16
    for (int s = 0; s < 64; ++s)
        sab += g_SabsPart[(b * 64 + s) * HID_ + h];

    const float4* lp = (const float4*)(g_LinPart + (b * HID_ + h) * 8);
    float4 l0 = lp[0], l1 = lp[1];
    float lin = ((l0.x + l0.y) + (l0.z + l0.w)) + ((l1.x + l1.y) + (l1.z + l1.w));
    lin += g_C[b * HID_ + h] * (float)R_PAIRS;
    Ss[h] = 0.5f * (lin + sab);
    __syncthreads();

    if (h < OUT_) {
        int o = h;
        const float4* wv = (const float4*)(W2 + o * HID_);
        const float4* sv = (const float4*)Ss;
        float acc = 0.0f;
#pragma unroll
        for (int q2 = 0; q2 < HID_ / 4; ++q2) {
            float4 ww = wv[q2]; float4 ssv = sv[q2];
            acc += ww.x * ssv.x + ww.y * ssv.y + ww.z * ssv.z + ww.w * ssv.w;
        }
        out[b * OUT_ + o] = acc + (float)R_PAIRS * b2[o];
    }
}

// ---------------------------------------------------------------------------
extern "C" void kernel_launch(void* const* d_in, const int* in_sizes, int n_in,
                              void* d_out, int out_size) {
    const float* x   = (const float*)d_in[0];
    const float* emb = (const float*)d_in[1];
    const float* W1  = (const float*)d_in[2];
    const float* b1  = (const float*)d_in[3];
    const float* W2  = (const float*)d_in[4];
    const float* b2  = (const float*)d_in[5];
    float* out = (float*)d_out;

    uv_kernel<<<1024, 256>>>(x, emb, W1, b1);
    pair_kernel<<<1024, 256>>>();
    out_kernel<<<B_, 128>>>(W2, b2, out);
}

// round 8
// speedup vs baseline: 1.1426x; 1.1260x over previous
#include <cuda_runtime.h>

#define B_      16
#define D_      64
#define N_      256
#define E_      64
#define HID_    128
#define OUT_    64
#define IN_     192
#define R_PAIRS 32640
#define XS_PAD  68
#define UV_PAD  18

// Scratch. U,V layout: [b][n][h] (h contiguous)
__device__ float g_U[B_ * N_ * HID_];
__device__ float g_V[B_ * N_ * HID_];
__device__ float g_C[B_ * HID_];
__device__ float g_LinPart[B_ * HID_ * 2];        // [(b*HID+h)*2 + ntq]
__device__ float g_SabsPart[B_ * 64 * HID_];      // [(b*64 + tp*4+jq)*HID + h]

// ---------------- packed f32x2 helpers ----------------
__device__ __forceinline__ void fma2(unsigned long long& acc,
                                     unsigned long long w, unsigned long long x) {
    asm("fma.rn.f32x2 %0, %1, %2, %3;" : "=l"(acc) : "l"(w), "l"(x), "l"(acc));
}
__device__ __forceinline__ unsigned long long pack2(float a, float b) {
    unsigned long long r;
    asm("mov.b64 %0, {%1, %2};" : "=l"(r) : "f"(a), "f"(b));
    return r;
}
__device__ __forceinline__ float lo2(unsigned long long v) {
    return __uint_as_float((unsigned)(v & 0xffffffffu));
}
__device__ __forceinline__ float hi2(unsigned long long v) {
    return __uint_as_float((unsigned)(v >> 32));
}
__device__ __forceinline__ void addabs2(unsigned long long& acc,
                                        unsigned long long t2, unsigned long long v2,
                                        unsigned long long mask) {
    unsigned long long x;
    asm("add.rn.f32x2 %0, %1, %2;" : "=l"(x) : "l"(t2), "l"(v2));
    asm("and.b64 %0, %1, %2;" : "=l"(x) : "l"(x), "l"(mask));
    asm("add.rn.f32x2 %0, %1, %2;" : "=l"(acc) : "l"(acc), "l"(x));
}

// ===========================================================================
// Kernel 1: U,V (transposed), C, lin partials.
// grid = 256 = (b:16, hg:8, ntq:2); block = 256.
// Warp computes 2 h over 4 n-tiles (128 n) => W1 uniform loads amortized 4x.
// ===========================================================================
__global__ __launch_bounds__(256, 2) void uv_kernel(
    const float* __restrict__ x, const float* __restrict__ emb,
    const float* __restrict__ W1, const float* __restrict__ b1)
{
    __shared__ __align__(16) float xs[128 * XS_PAD];   // 34.8 KB (reused for u/v)
    const int bx   = blockIdx.x;
    const int ntq  = bx & 1;
    const int hg   = (bx >> 1) & 7;
    const int b    = bx >> 4;
    const int tid  = threadIdx.x;
    const int w    = tid >> 5;
    const int lane = tid & 31;
    const int n0g  = ntq * 128;

    // C[b][h] for this hg (done by the ntq==0 block)
    if (ntq == 0 && tid < 16) {
        int h = hg * 16 + tid;
        const float4* wr = (const float4*)(W1 + h * IN_ + 2 * D_);
        const float4* er = (const float4*)(emb + b * E_);
        float acc = b1[h];
#pragma unroll
        for (int e4 = 0; e4 < E_ / 4; ++e4) {
            float4 ww = wr[e4]; float4 ee = er[e4];
            acc += ww.x * ee.x + ww.y * ee.y + ww.z * ee.z + ww.w * ee.w;
        }
        g_C[b * HID_ + h] = acc;
    }

    // stage x[b][0:64][n0g:n0g+128] transposed into xs[n][d]
    {
        const float4* xg = (const float4*)(x + b * D_ * N_ + n0g);
#pragma unroll
        for (int t = tid; t < 2048; t += 256) {
            int d  = t >> 5;          // 0..63
            int c4 = t & 31;          // float4 column 0..31
            float4 vv = xg[d * (N_ / 4) + c4];
            int nl = c4 * 4;
            xs[(nl + 0) * XS_PAD + d] = vv.x;
            xs[(nl + 1) * XS_PAD + d] = vv.y;
            xs[(nl + 2) * XS_PAD + d] = vv.z;
            xs[(nl + 3) * XS_PAD + d] = vv.w;
        }
    }
    __syncthreads();

    const int h1 = hg * 16 + w;
    const int h2 = h1 + 8;
    const ulonglong2* wa1 = (const ulonglong2*)(W1 + h1 * IN_);
    const ulonglong2* wb1 = (const ulonglong2*)(W1 + h1 * IN_ + D_);
    const ulonglong2* wa2 = (const ulonglong2*)(W1 + h2 * IN_);
    const ulonglong2* wb2 = (const ulonglong2*)(W1 + h2 * IN_ + D_);
    const ulonglong2* xr0 = (const ulonglong2*)(xs + (lane +  0) * XS_PAD);
    const ulonglong2* xr1 = (const ulonglong2*)(xs + (lane + 32) * XS_PAD);
    const ulonglong2* xr2 = (const ulonglong2*)(xs + (lane + 64) * XS_PAD);
    const ulonglong2* xr3 = (const ulonglong2*)(xs + (lane + 96) * XS_PAD);

    unsigned long long au1[4] = {0,0,0,0}, av1[4] = {0,0,0,0};
    unsigned long long au2[4] = {0,0,0,0}, av2[4] = {0,0,0,0};
#pragma unroll
    for (int d4 = 0; d4 < 16; ++d4) {
        ulonglong2 A1 = wa1[d4], B1 = wb1[d4];
        ulonglong2 A2 = wa2[d4], B2 = wb2[d4];
        ulonglong2 x0 = xr0[d4], x1 = xr1[d4], x2 = xr2[d4], x3 = xr3[d4];
        fma2(au1[0], A1.x, x0.x); fma2(au1[0], A1.y, x0.y);
        fma2(av1[0], B1.x, x0.x); fma2(av1[0], B1.y, x0.y);
        fma2(au2[0], A2.x, x0.x); fma2(au2[0], A2.y, x0.y);
        fma2(av2[0], B2.x, x0.x); fma2(av2[0], B2.y, x0.y);
        fma2(au1[1], A1.x, x1.x); fma2(au1[1], A1.y, x1.y);
        fma2(av1[1], B1.x, x1.x); fma2(av1[1], B1.y, x1.y);
        fma2(au2[1], A2.x, x1.x); fma2(au2[1], A2.y, x1.y);
        fma2(av2[1], B2.x, x1.x); fma2(av2[1], B2.y, x1.y);
        fma2(au1[2], A1.x, x2.x); fma2(au1[2], A1.y, x2.y);
        fma2(av1[2], B1.x, x2.x); fma2(av1[2], B1.y, x2.y);
        fma2(au2[2], A2.x, x2.x); fma2(au2[2], A2.y, x2.y);
        fma2(av2[2], B2.x, x2.x); fma2(av2[2], B2.y, x2.y);
        fma2(au1[3], A1.x, x3.x); fma2(au1[3], A1.y, x3.y);
        fma2(av1[3], B1.x, x3.x); fma2(av1[3], B1.y, x3.y);
        fma2(au2[3], A2.x, x3.x); fma2(au2[3], A2.y, x3.y);
        fma2(av2[3], B2.x, x3.x); fma2(av2[3], B2.y, x3.y);
    }

    float u1[4], v1[4], u2[4], v2[4];
    float lin1 = 0.0f, lin2 = 0.0f;
#pragma unroll
    for (int t = 0; t < 4; ++t) {
        u1[t] = lo2(au1[t]) + hi2(au1[t]);
        v1[t] = lo2(av1[t]) + hi2(av1[t]);
        u2[t] = lo2(au2[t]) + hi2(au2[t]);
        v2[t] = lo2(av2[t]) + hi2(av2[t]);
        float nf = (float)(n0g + t * 32 + lane);
        lin1 += u1[t] * (255.0f - nf) + v1[t] * nf;
        lin2 += u2[t] * (255.0f - nf) + v2[t] * nf;
    }
#pragma unroll
    for (int o = 16; o; o >>= 1) {
        lin1 += __shfl_xor_sync(0xffffffffu, lin1, o);
        lin2 += __shfl_xor_sync(0xffffffffu, lin2, o);
    }
    if (lane == 0) {
        g_LinPart[(b * HID_ + h1) * 2 + ntq] = lin1;
        g_LinPart[(b * HID_ + h2) * 2 + ntq] = lin2;
    }

    // transpose to [n][h] via smem (reuse xs), then coalesced STG.64
    __syncthreads();   // everyone done reading xs
    float* us = xs;                       // 128 x UV_PAD
    float* vs = xs + 128 * UV_PAD;
#pragma unroll
    for (int t = 0; t < 4; ++t) {
        int r = t * 32 + lane;
        us[r * UV_PAD + w]     = u1[t];
        us[r * UV_PAD + w + 8] = u2[t];
        vs[r * UV_PAD + w]     = v1[t];
        vs[r * UV_PAD + w + 8] = v2[t];
    }
    __syncthreads();
#pragma unroll
    for (int t2 = tid; t2 < 128 * 8; t2 += 256) {
        int n  = t2 >> 3;
        int hp = t2 & 7;
        float2 uu = *(const float2*)(us + n * UV_PAD + 2 * hp);
        float2 vv = *(const float2*)(vs + n * UV_PAD + 2 * hp);
        int row = b * N_ + n0g + n;
        ((float2*)g_U)[row * (HID_ / 2) + hg * 8 + hp] = uu;
        ((float2*)g_V)[row * (HID_ / 2) + hg * 8 + hp] = vv;
    }
}

// ===========================================================================
// Kernel 2: Sabs partials.
// grid = 1024 = (b:16, tp:16, jq:4); block = 256 (8 warps).
// warp w: tile_sel=w&1, hhalf=(w>>1)&1, jhalf=w>>2; tiles {tp, 31-tp}.
// Register double-buffered j-loads (1 iteration lookahead).
// ===========================================================================
__global__ __launch_bounds__(256, 4) void pair_kernel()
{
    __shared__ float2 red[8][32];
    const unsigned long long mask = 0x7FFFFFFF7FFFFFFFull;
    const int bx   = blockIdx.x;
    const int jq   = bx & 3;
    const int tp   = (bx >> 2) & 15;
    const int b    = bx >> 6;
    const int tid  = threadIdx.x;
    const int w    = tid >> 5;
    const int lane = tid & 31;

    const int ts   = w & 1;
    const int hh   = (w >> 1) & 1;
    const int jh   = w >> 2;
    const int tile = ts ? (31 - tp) : tp;
    const int hp   = hh * 32 + lane;

    const int i0   = tile * 8;
    const int jbeg = i0 + 8;
    const int len  = N_ - jbeg;               // multiple of 8 (0 for tile 31)
    const int q    = len >> 3;
    const int pi   = jq * 2 + jh;
    const int jlo  = jbeg + pi * q;
    const int jhi  = jlo + q;

    const float2* U2 = (const float2*)g_U + (size_t)b * N_ * (HID_ / 2) + hp;
    const unsigned long long* V2 =
        (const unsigned long long*)g_V + (size_t)b * N_ * (HID_ / 2) + hp;
    float2 cc = ((const float2*)g_C)[b * (HID_ / 2) + hp];

    unsigned long long t2[8], a2[8];
#pragma unroll
    for (int k = 0; k < 8; ++k) {
        float2 uu = U2[(i0 + k) * (HID_ / 2)];
        t2[k] = pack2(uu.x + cc.x, uu.y + cc.y);
        a2[k] = 0ull;
    }

    // triangular corner: piece 0 only
    if (pi == 0) {
#pragma unroll
        for (int jj = 1; jj < 8; ++jj) {
            unsigned long long v2 = V2[(i0 + jj) * (HID_ / 2)];
#pragma unroll
            for (int k = 0; k < jj; ++k) addabs2(a2[k], t2[k], v2, mask);
        }
    }

    // main loop: 4 j per iteration, double-buffered loads
    int j = jlo;
    if (j + 4 <= jhi) {
        unsigned long long c0 = V2[(j + 0) * (HID_ / 2)];
        unsigned long long c1 = V2[(j + 1) * (HID_ / 2)];
        unsigned long long c2 = V2[(j + 2) * (HID_ / 2)];
        unsigned long long c3 = V2[(j + 3) * (HID_ / 2)];
        for (; j + 8 <= jhi; j += 4) {
            unsigned long long n0 = V2[(j + 4) * (HID_ / 2)];
            unsigned long long n1 = V2[(j + 5) * (HID_ / 2)];
            unsigned long long n2 = V2[(j + 6) * (HID_ / 2)];
            unsigned long long n3 = V2[(j + 7) * (HID_ / 2)];
#pragma unroll
            for (int k = 0; k < 8; ++k) {
                addabs2(a2[k], t2[k], c0, mask);
                addabs2(a2[k], t2[k], c1, mask);
                addabs2(a2[k], t2[k], c2, mask);
                addabs2(a2[k], t2[k], c3, mask);
            }
            c0 = n0; c1 = n1; c2 = n2; c3 = n3;
        }
#pragma unroll
        for (int k = 0; k < 8; ++k) {
            addabs2(a2[k], t2[k], c0, mask);
            addabs2(a2[k], t2[k], c1, mask);
            addabs2(a2[k], t2[k], c2, mask);
            addabs2(a2[k], t2[k], c3, mask);
        }
        j += 4;
    }
    for (; j < jhi; ++j) {
        unsigned long long p0 = V2[j * (HID_ / 2)];
#pragma unroll
        for (int k = 0; k < 8; ++k) addabs2(a2[k], t2[k], p0, mask);
    }

    // per-warp packed sum, then combine 4 warps per hhalf
    unsigned long long s2 = a2[0];
#pragma unroll
    for (int k = 1; k < 8; ++k)
        asm("add.rn.f32x2 %0, %1, %2;" : "=l"(s2) : "l"(s2), "l"(a2[k]));
    red[w][lane] = make_float2(lo2(s2), hi2(s2));
    __syncthreads();

    if (tid < 64) {
        int hh2 = tid >> 5;            // hhalf
        int l   = tid & 31;
        int base = hh2 * 2;            // warps {2hh, 2hh+1, 2hh+4, 2hh+5}
        float2 A  = red[base + 0][l];
        float2 Bv = red[base + 1][l];
        float2 Cv = red[base + 4][l];
        float2 Dv = red[base + 5][l];
        float2 r;
        r.x = (A.x + Bv.x) + (Cv.x + Dv.x);
        r.y = (A.y + Bv.y) + (Cv.y + Dv.y);
        int slot = b * 64 + tp * 4 + jq;
        ((float2*)g_SabsPart)[slot * (HID_ / 2) + hh2 * 32 + l] = r;
    }
}

// ===========================================================================
// Kernel 3: reduce partials + output GEMM. grid = 16, block = 128.
// ===========================================================================
__global__ __launch_bounds__(128) void out_kernel(
    const float* __restrict__ W2, const float* __restrict__ b2,
    float* __restrict__ out)
{
    __shared__ float Ss[HID_];
    const int b = blockIdx.x;
    const int h = threadIdx.x;

    float sab = 0.0f;
#pragma unroll 16
    for (int s = 0; s < 64; ++s)
        sab += g_SabsPart[(b * 64 + s) * HID_ + h];

    float lin = g_LinPart[(b * HID_ + h) * 2 + 0]
              + g_LinPart[(b * HID_ + h) * 2 + 1];
    lin += g_C[b * HID_ + h] * (float)R_PAIRS;
    Ss[h] = 0.5f * (lin + sab);
    __syncthreads();

    if (h < OUT_) {
        int o = h;
        const float4* wv = (const float4*)(W2 + o * HID_);
        const float4* sv = (const float4*)Ss;
        float acc = 0.0f;
#pragma unroll
        for (int q2 = 0; q2 < HID_ / 4; ++q2) {
            float4 ww = wv[q2]; float4 ssv = sv[q2];
            acc += ww.x * ssv.x + ww.y * ssv.y + ww.z * ssv.z + ww.w * ssv.w;
        }
        out[b * OUT_ + o] = acc + (float)R_PAIRS * b2[o];
    }
}

// ---------------------------------------------------------------------------
extern "C" void kernel_launch(void* const* d_in, const int* in_sizes, int n_in,
                              void* d_out, int out_size) {
    const float* x   = (const float*)d_in[0];
    const float* emb = (const float*)d_in[1];
    const float* W1  = (const float*)d_in[2];
    const float* b1  = (const float*)d_in[3];
    const float* W2  = (const float*)d_in[4];
    const float* b2  = (const float*)d_in[5];
    float* out = (float*)d_out;

    uv_kernel<<<256, 256>>>(x, emb, W1, b1);
    pair_kernel<<<1024, 256>>>();
    out_kernel<<<B_, 128>>>(W2, b2, out);
}

// round 9
// speedup vs baseline: 1.1747x; 1.0281x over previous
#include <cuda_runtime.h>

#define B_      16
#define D_      64
#define N_      256
#define E_      64
#define HID_    128
#define OUT_    64
#define IN_     192
#define R_PAIRS 32640
#define UV_PAD  18

// Scratch. U,V layout: [b][n][h] (h contiguous)
__device__ float g_U[B_ * N_ * HID_];
__device__ float g_V[B_ * N_ * HID_];
__device__ float g_C[B_ * HID_];
__device__ float g_LinPart[B_ * HID_ * 4];        // [(b*HID+h)*4 + ntq]
__device__ float g_SabsPart[B_ * 64 * HID_];      // [(b*64 + tp*4+jq)*HID + h]

// ---------------- packed f32x2 helpers ----------------
__device__ __forceinline__ void fma2(unsigned long long& acc,
                                     unsigned long long w, unsigned long long x) {
    asm("fma.rn.f32x2 %0, %1, %2, %3;" : "=l"(acc) : "l"(w), "l"(x), "l"(acc));
}
__device__ __forceinline__ unsigned long long pack2(float a, float b) {
    unsigned long long r;
    asm("mov.b64 %0, {%1, %2};" : "=l"(r) : "f"(a), "f"(b));
    return r;
}
__device__ __forceinline__ float lo2(unsigned long long v) {
    return __uint_as_float((unsigned)(v & 0xffffffffu));
}
__device__ __forceinline__ float hi2(unsigned long long v) {
    return __uint_as_float((unsigned)(v >> 32));
}
__device__ __forceinline__ void addabs2(unsigned long long& acc,
                                        unsigned long long t2, unsigned long long v2,
                                        unsigned long long mask) {
    unsigned long long x;
    asm("add.rn.f32x2 %0, %1, %2;" : "=l"(x) : "l"(t2), "l"(v2));
    asm("and.b64 %0, %1, %2;" : "=l"(x) : "l"(x), "l"(mask));
    asm("add.rn.f32x2 %0, %1, %2;" : "=l"(acc) : "l"(acc), "l"(x));
}

// ===========================================================================
// Kernel 1: U,V + C + lin partials. N-PACKED: no x transpose, no staging-in.
// grid = 512 = (b:16, hgq:8 -> 16 h, ntq:4 -> 64 n); block = 256 (8 warps).
// Warp: 2 h over 64 n (lane = n-pair). x read directly from gmem (coalesced
// LDG.64); W1 duplicated into smem once per block (uniform LDS.128 reads).
// ===========================================================================
__global__ __launch_bounds__(256, 4) void uv_kernel(
    const float* __restrict__ x, const float* __restrict__ emb,
    const float* __restrict__ W1, const float* __restrict__ b1)
{
    __shared__ __align__(16) unsigned long long ws[16 * 2 * 64];  // 16 KB
    const int bx   = blockIdx.x;
    const int ntq  = bx & 3;
    const int hgq  = (bx >> 2) & 7;
    const int b    = bx >> 5;
    const int tid  = threadIdx.x;
    const int w    = tid >> 5;
    const int lane = tid & 31;
    const int n0g  = ntq * 64;
    const int hbase = hgq * 16;

    // C[b][h] for this h-group (ntq==0 blocks only)
    if (ntq == 0 && tid < 16) {
        int h = hbase + tid;
        const float4* wr = (const float4*)(W1 + h * IN_ + 2 * D_);
        const float4* er = (const float4*)(emb + b * E_);
        float acc = b1[h];
#pragma unroll
        for (int e4 = 0; e4 < E_ / 4; ++e4) {
            float4 ww = wr[e4]; float4 ee = er[e4];
            acc += ww.x * ee.x + ww.y * ee.y + ww.z * ee.z + ww.w * ee.w;
        }
        g_C[b * HID_ + h] = acc;
    }

    // Build duplicated-W table: ws[hl*128 + ab*64 + d] = (W,W)
#pragma unroll
    for (int i = 0; i < 8; ++i) {
        int idx = i * 256 + tid;
        int hl = idx >> 7;
        int ab = (idx >> 6) & 1;
        int d  = idx & 63;
        float wv = W1[(hbase + hl) * IN_ + ab * 64 + d];
        ws[idx] = pack2(wv, wv);
    }
    __syncthreads();

    const int hl1 = 2 * w, hl2 = 2 * w + 1;
    const ulonglong2* wsA1 = (const ulonglong2*)(ws + hl1 * 128);
    const ulonglong2* wsB1 = (const ulonglong2*)(ws + hl1 * 128 + 64);
    const ulonglong2* wsA2 = (const ulonglong2*)(ws + hl2 * 128);
    const ulonglong2* wsB2 = (const ulonglong2*)(ws + hl2 * 128 + 64);
    const float* xp = x + b * D_ * N_ + n0g + 2 * lane;

    unsigned long long au1 = 0ull, av1 = 0ull, au2 = 0ull, av2 = 0ull;
#pragma unroll 8
    for (int d2 = 0; d2 < 32; ++d2) {
        ulonglong2 A1 = wsA1[d2], B1v = wsB1[d2];
        ulonglong2 A2 = wsA2[d2], B2v = wsB2[d2];
        unsigned long long x0 = *(const unsigned long long*)(xp + (2 * d2) * N_);
        unsigned long long x1 = *(const unsigned long long*)(xp + (2 * d2 + 1) * N_);
        fma2(au1, A1.x,  x0); fma2(au1, A1.y,  x1);
        fma2(av1, B1v.x, x0); fma2(av1, B1v.y, x1);
        fma2(au2, A2.x,  x0); fma2(au2, A2.y,  x1);
        fma2(av2, B2v.x, x0); fma2(av2, B2v.y, x1);
    }

    // lin partials: sum over this warp's 64 n of u*(255-n) + v*n  (packed)
    {
        float nf = (float)(n0g + 2 * lane);
        unsigned long long cu = pack2(255.0f - nf, 254.0f - nf);
        unsigned long long cv = pack2(nf, nf + 1.0f);
        unsigned long long l1 = 0ull, l2 = 0ull;
        fma2(l1, au1, cu); fma2(l1, av1, cv);
        fma2(l2, au2, cu); fma2(l2, av2, cv);
        float lin1 = lo2(l1) + hi2(l1);
        float lin2 = lo2(l2) + hi2(l2);
#pragma unroll
        for (int o = 16; o; o >>= 1) {
            lin1 += __shfl_xor_sync(0xffffffffu, lin1, o);
            lin2 += __shfl_xor_sync(0xffffffffu, lin2, o);
        }
        if (lane == 0) {
            g_LinPart[(b * HID_ + hbase + hl1) * 4 + ntq] = lin1;
            g_LinPart[(b * HID_ + hbase + hl2) * 4 + ntq] = lin2;
        }
    }

    // stage to [n][h] (overlay on ws; all warps done reading it)
    __syncthreads();
    float* us = (float*)ws;                  // 64 x UV_PAD
    float* vs = (float*)ws + 64 * UV_PAD;
    {
        int r = 2 * lane;
        us[r * UV_PAD + hl1]       = lo2(au1);
        us[(r + 1) * UV_PAD + hl1] = hi2(au1);
        us[r * UV_PAD + hl2]       = lo2(au2);
        us[(r + 1) * UV_PAD + hl2] = hi2(au2);
        vs[r * UV_PAD + hl1]       = lo2(av1);
        vs[(r + 1) * UV_PAD + hl1] = hi2(av1);
        vs[r * UV_PAD + hl2]       = lo2(av2);
        vs[(r + 1) * UV_PAD + hl2] = hi2(av2);
    }
    __syncthreads();
#pragma unroll
    for (int i2 = 0; i2 < 2; ++i2) {
        int t  = i2 * 256 + tid;             // 0..511 = 64 n x 8 hp
        int n  = t >> 3;
        int hp = t & 7;
        float2 uu = *(const float2*)(us + n * UV_PAD + 2 * hp);
        float2 vv = *(const float2*)(vs + n * UV_PAD + 2 * hp);
        int row = b * N_ + n0g + n;
        ((float2*)g_U)[row * (HID_ / 2) + hgq * 8 + hp] = uu;
        ((float2*)g_V)[row * (HID_ / 2) + hgq * 8 + hp] = vv;
    }
}

// ===========================================================================
// Kernel 2: Sabs partials (UNCHANGED from R8).
// grid = 1024 = (b:16, tp:16, jq:4); block = 256 (8 warps).
// ===========================================================================
__global__ __launch_bounds__(256, 4) void pair_kernel()
{
    __shared__ float2 red[8][32];
    const unsigned long long mask = 0x7FFFFFFF7FFFFFFFull;
    const int bx   = blockIdx.x;
    const int jq   = bx & 3;
    const int tp   = (bx >> 2) & 15;
    const int b    = bx >> 6;
    const int tid  = threadIdx.x;
    const int w    = tid >> 5;
    const int lane = tid & 31;

    const int ts   = w & 1;
    const int hh   = (w >> 1) & 1;
    const int jh   = w >> 2;
    const int tile = ts ? (31 - tp) : tp;
    const int hp   = hh * 32 + lane;

    const int i0   = tile * 8;
    const int jbeg = i0 + 8;
    const int len  = N_ - jbeg;
    const int q    = len >> 3;
    const int pi   = jq * 2 + jh;
    const int jlo  = jbeg + pi * q;
    const int jhi  = jlo + q;

    const float2* U2 = (const float2*)g_U + (size_t)b * N_ * (HID_ / 2) + hp;
    const unsigned long long* V2 =
        (const unsigned long long*)g_V + (size_t)b * N_ * (HID_ / 2) + hp;
    float2 cc = ((const float2*)g_C)[b * (HID_ / 2) + hp];

    unsigned long long t2[8], a2[8];
#pragma unroll
    for (int k = 0; k < 8; ++k) {
        float2 uu = U2[(i0 + k) * (HID_ / 2)];
        t2[k] = pack2(uu.x + cc.x, uu.y + cc.y);
        a2[k] = 0ull;
    }

    if (pi == 0) {
#pragma unroll
        for (int jj = 1; jj < 8; ++jj) {
            unsigned long long v2 = V2[(i0 + jj) * (HID_ / 2)];
#pragma unroll
            for (int k = 0; k < jj; ++k) addabs2(a2[k], t2[k], v2, mask);
        }
    }

    int j = jlo;
    if (j + 4 <= jhi) {
        unsigned long long c0 = V2[(j + 0) * (HID_ / 2)];
        unsigned long long c1 = V2[(j + 1) * (HID_ / 2)];
        unsigned long long c2 = V2[(j + 2) * (HID_ / 2)];
        unsigned long long c3 = V2[(j + 3) * (HID_ / 2)];
        for (; j + 8 <= jhi; j += 4) {
            unsigned long long n0 = V2[(j + 4) * (HID_ / 2)];
            unsigned long long n1 = V2[(j + 5) * (HID_ / 2)];
            unsigned long long n2 = V2[(j + 6) * (HID_ / 2)];
            unsigned long long n3 = V2[(j + 7) * (HID_ / 2)];
#pragma unroll
            for (int k = 0; k < 8; ++k) {
                addabs2(a2[k], t2[k], c0, mask);
                addabs2(a2[k], t2[k], c1, mask);
                addabs2(a2[k], t2[k], c2, mask);
                addabs2(a2[k], t2[k], c3, mask);
            }
            c0 = n0; c1 = n1; c2 = n2; c3 = n3;
        }
#pragma unroll
        for (int k = 0; k < 8; ++k) {
            addabs2(a2[k], t2[k], c0, mask);
            addabs2(a2[k], t2[k], c1, mask);
            addabs2(a2[k], t2[k], c2, mask);
            addabs2(a2[k], t2[k], c3, mask);
        }
        j += 4;
    }
    for (; j < jhi; ++j) {
        unsigned long long p0 = V2[j * (HID_ / 2)];
#pragma unroll
        for (int k = 0; k < 8; ++k) addabs2(a2[k], t2[k], p0, mask);
    }

    unsigned long long s2 = a2[0];
#pragma unroll
    for (int k = 1; k < 8; ++k)
        asm("add.rn.f32x2 %0, %1, %2;" : "=l"(s2) : "l"(s2), "l"(a2[k]));
    red[w][lane] = make_float2(lo2(s2), hi2(s2));
    __syncthreads();

    if (tid < 64) {
        int hh2 = tid >> 5;
        int l   = tid & 31;
        int base = hh2 * 2;
        float2 A  = red[base + 0][l];
        float2 Bv = red[base + 1][l];
        float2 Cv = red[base + 4][l];
        float2 Dv = red[base + 5][l];
        float2 r;
        r.x = (A.x + Bv.x) + (Cv.x + Dv.x);
        r.y = (A.y + Bv.y) + (Cv.y + Dv.y);
        int slot = b * 64 + tp * 4 + jq;
        ((float2*)g_SabsPart)[slot * (HID_ / 2) + hh2 * 32 + l] = r;
    }
}

// ===========================================================================
// Kernel 3: reduce partials + output GEMM. grid = 16, block = 256.
// ===========================================================================
__global__ __launch_bounds__(256) void out_kernel(
    const float* __restrict__ W2, const float* __restrict__ b2,
    float* __restrict__ out)
{
    __shared__ float Sred[2][HID_];
    __shared__ float Ss[HID_];
    const int b    = blockIdx.x;
    const int tid  = threadIdx.x;
    const int h    = tid & 127;
    const int half = tid >> 7;

    float sab = 0.0f;
#pragma unroll 8
    for (int s = half * 32; s < half * 32 + 32; ++s)
        sab += g_SabsPart[(b * 64 + s) * HID_ + h];
    Sred[half][h] = sab;
    __syncthreads();

    if (tid < HID_) {
        float sab2 = Sred[0][h] + Sred[1][h];
        const float4* lp = (const float4*)(g_LinPart + (b * HID_ + h) * 4);
        float4 l = lp[0];
        float lin = (l.x + l.y) + (l.z + l.w);
        lin += g_C[b * HID_ + h] * (float)R_PAIRS;
        Ss[h] = 0.5f * (lin + sab2);
    }
    __syncthreads();

    if (tid < OUT_) {
        int o = tid;
        const float4* wv = (const float4*)(W2 + o * HID_);
        const float4* sv = (const float4*)Ss;
        float acc = 0.0f;
#pragma unroll
        for (int q2 = 0; q2 < HID_ / 4; ++q2) {
            float4 ww = wv[q2]; float4 ssv = sv[q2];
            acc += ww.x * ssv.x + ww.y * ssv.y + ww.z * ssv.z + ww.w * ssv.w;
        }
        out[b * OUT_ + o] = acc + (float)R_PAIRS * b2[o];
    }
}

// ---------------------------------------------------------------------------
extern "C" void kernel_launch(void* const* d_in, const int* in_sizes, int n_in,
                              void* d_out, int out_size) {
    const float* x   = (const float*)d_in[0];
    const float* emb = (const float*)d_in[1];
    const float* W1  = (const float*)d_in[2];
    const float* b1  = (const float*)d_in[3];
    const float* W2  = (const float*)d_in[4];
    const float* b2  = (const float*)d_in[5];
    float* out = (float*)d_out;

    uv_kernel<<<512, 256>>>(x, emb, W1, b1);
    pair_kernel<<<1024, 256>>>();
    out_kernel<<<B_, 256>>>(W2, b2, out);
}

// round 11
// speedup vs baseline: 1.5918x; 1.3551x over previous
#include <cuda_runtime.h>

#define B_      16
#define D_      64
#define N_      256
#define E_      64
#define HID_    128
#define OUT_    64
#define IN_     192
#define R_PAIRS 32640
#define UV_PAD  18

// Only cross-kernel scratch: the pre-GEMM vector S[b][h]
__device__ float g_S[B_ * HID_];

// ---- dynamic smem layout (bytes) ----
#define OFF_XS   0                       // 64*256 floats   = 65536
#define OFF_WT   65536                   // 2048 ull        = 16384
#define OFF_US   81920                   // 256*18 floats   = 18432
#define OFF_VS   100352                  // 256*18 floats   = 18432
#define OFF_CS   118784                  // 16 floats       = 64
#define OFF_LIN  118848                  // 64 floats       = 256
#define OFF_RED  119104                  // 16*8 float2     = 1024  (was the R10 bug: 256)
#define SMEM_TOT 120128

// ---------------- packed f32x2 helpers ----------------
__device__ __forceinline__ void fma2(unsigned long long& acc,
                                     unsigned long long w, unsigned long long x) {
    asm("fma.rn.f32x2 %0, %1, %2, %3;" : "=l"(acc) : "l"(w), "l"(x), "l"(acc));
}
__device__ __forceinline__ unsigned long long pack2(float a, float b) {
    unsigned long long r;
    asm("mov.b64 %0, {%1, %2};" : "=l"(r) : "f"(a), "f"(b));
    return r;
}
__device__ __forceinline__ float lo2(unsigned long long v) {
    return __uint_as_float((unsigned)(v & 0xffffffffu));
}
__device__ __forceinline__ float hi2(unsigned long long v) {
    return __uint_as_float((unsigned)(v >> 32));
}
__device__ __forceinline__ unsigned long long padd2(unsigned long long a,
                                                    unsigned long long b) {
    unsigned long long r;
    asm("add.rn.f32x2 %0, %1, %2;" : "=l"(r) : "l"(a), "l"(b));
    return r;
}
__device__ __forceinline__ void addabs2(unsigned long long& acc,
                                        unsigned long long t2, unsigned long long v2,
                                        unsigned long long mask) {
    unsigned long long x;
    asm("add.rn.f32x2 %0, %1, %2;" : "=l"(x) : "l"(t2), "l"(v2));
    asm("and.b64 %0, %1, %2;" : "=l"(x) : "l"(x), "l"(mask));
    asm("add.rn.f32x2 %0, %1, %2;" : "=l"(acc) : "l"(acc), "l"(x));
}

// ===========================================================================
// Fused kernel: per (b, hg of 16 h) everything up to S[b][h].
// grid = 128 = (b:16, hg:8); block = 512 (16 warps).
// ===========================================================================
__global__ __launch_bounds__(512, 1) void fused_kernel(
    const float* __restrict__ x, const float* __restrict__ emb,
    const float* __restrict__ W1, const float* __restrict__ b1)
{
    extern __shared__ __align__(16) char smem[];
    float*              xs  = (float*)(smem + OFF_XS);    // [d][256 n]
    unsigned long long* wt  = (unsigned long long*)(smem + OFF_WT); // [16h][2ab][64d] dup
    float*              us  = (float*)(smem + OFF_US);    // [256 n][18]
    float*              vs  = (float*)(smem + OFF_VS);
    float*              cs  = (float*)(smem + OFF_CS);    // [16]
    float*              lr  = (float*)(smem + OFF_LIN);   // [16h][4nq]
    float2*             red = (float2*)(smem + OFF_RED);  // [16w][8hp]

    const int bx    = blockIdx.x;
    const int hg    = bx & 7;
    const int b     = bx >> 3;
    const int hbase = hg * 16;
    const int tid   = threadIdx.x;
    const int w     = tid >> 5;
    const int lane  = tid & 31;

    // ---- stage x[b] (straight 64 KB copy) ----
    {
        const float4* xg = (const float4*)(x + b * D_ * N_);
        float4*       xd = (float4*)xs;
#pragma unroll
        for (int i = 0; i < 8; ++i)
            xd[i * 512 + tid] = xg[i * 512 + tid];
    }
    // ---- build duplicated W table ----
#pragma unroll
    for (int i = 0; i < 4; ++i) {
        int idx = i * 512 + tid;               // hl*128 + ab*64 + d
        int hl  = idx >> 7;
        int ab  = (idx >> 6) & 1;
        int d   = idx & 63;
        float wv = W1[(hbase + hl) * IN_ + ab * 64 + d];
        wt[idx] = pack2(wv, wv);
    }
    // ---- C for these 16 h ----
    if (tid < 16) {
        int h = hbase + tid;
        const float4* wr = (const float4*)(W1 + h * IN_ + 2 * D_);
        const float4* er = (const float4*)(emb + b * E_);
        float acc = b1[h];
#pragma unroll
        for (int e4 = 0; e4 < E_ / 4; ++e4) {
            float4 ww = wr[e4]; float4 ee = er[e4];
            acc += ww.x * ee.x + ww.y * ee.y + ww.z * ee.z + ww.w * ee.w;
        }
        cs[tid] = acc;
    }
    __syncthreads();

    // ================= Phase A: U,V into smem + lin partials =================
    {
        const int hq = w >> 2;          // 0..3 -> 4 h
        const int nq = w & 3;           // 0..3 -> 64 n
        const int n0 = nq * 64 + 2 * lane;

        unsigned long long au[4] = {0,0,0,0}, av[4] = {0,0,0,0};
        const float* xpp = xs + n0;
#pragma unroll 4
        for (int d2 = 0; d2 < 32; ++d2) {
            unsigned long long x0 = *(const unsigned long long*)(xpp + (2 * d2)     * N_);
            unsigned long long x1 = *(const unsigned long long*)(xpp + (2 * d2 + 1) * N_);
#pragma unroll
            for (int hl = 0; hl < 4; ++hl) {
                const ulonglong2* wA = (const ulonglong2*)(wt + (hq * 4 + hl) * 128);
                const ulonglong2* wB = (const ulonglong2*)(wt + (hq * 4 + hl) * 128 + 64);
                ulonglong2 A = wA[d2], Bv = wB[d2];
                fma2(au[hl], A.x,  x0); fma2(au[hl], A.y,  x1);
                fma2(av[hl], Bv.x, x0); fma2(av[hl], Bv.y, x1);
            }
        }

        // lin partials
        float nf = (float)n0;
        unsigned long long cu = pack2(255.0f - nf, 254.0f - nf);
        unsigned long long cv = pack2(nf, nf + 1.0f);
#pragma unroll
        for (int hl = 0; hl < 4; ++hl) {
            unsigned long long l = 0ull;
            fma2(l, au[hl], cu); fma2(l, av[hl], cv);
            float lin = lo2(l) + hi2(l);
#pragma unroll
            for (int o = 16; o; o >>= 1)
                lin += __shfl_xor_sync(0xffffffffu, lin, o);
            if (lane == 0) lr[(hq * 4 + hl) * 4 + nq] = lin;
        }

        // store U,V to smem [n][16h] pad 18
#pragma unroll
        for (int hl = 0; hl < 4; ++hl) {
            int h = hq * 4 + hl;
            us[n0 * UV_PAD + h]       = lo2(au[hl]);
            us[(n0 + 1) * UV_PAD + h] = hi2(au[hl]);
            vs[n0 * UV_PAD + h]       = lo2(av[hl]);
            vs[(n0 + 1) * UV_PAD + h] = hi2(av[hl]);
        }
    }
    __syncthreads();

    // ================= Phase B: Sabs over all pairs (tiles {w, 31-w}) ========
    {
        const unsigned long long mask = 0x7FFFFFFF7FFFFFFFull;
        const int hp   = lane & 7;
        const int isub = lane >> 3;

        float2 ccf = *(const float2*)(cs + 2 * hp);
        unsigned long long ccp = pack2(ccf.x, ccf.y);

        unsigned long long aA = 0ull, aB = 0ull;
#pragma unroll
        for (int rep = 0; rep < 2; ++rep) {
            int tile = rep ? (31 - w) : w;
            int i0   = tile * 8;
            int ia   = i0 + 2 * isub;

            unsigned long long ua = *(const unsigned long long*)(us + ia * UV_PAD + 2 * hp);
            unsigned long long ub = *(const unsigned long long*)(us + (ia + 1) * UV_PAD + 2 * hp);
            unsigned long long tA = padd2(ua, ccp);
            unsigned long long tB = padd2(ub, ccp);

            // corner (within-tile pairs)
#pragma unroll
            for (int jj = 1; jj < 8; ++jj) {
                unsigned long long vj =
                    *(const unsigned long long*)(vs + (i0 + jj) * UV_PAD + 2 * hp);
                if (2 * isub < jj)     addabs2(aA, tA, vj, mask);
                if (2 * isub + 1 < jj) addabs2(aB, tB, vj, mask);
            }

            // main: j in [i0+8, 256), multiple of 8
            const float* vbase = vs + 2 * hp;
            for (int j = i0 + 8; j < N_; j += 4) {
                unsigned long long v0 = *(const unsigned long long*)(vbase + (j + 0) * UV_PAD);
                unsigned long long v1 = *(const unsigned long long*)(vbase + (j + 1) * UV_PAD);
                unsigned long long v2 = *(const unsigned long long*)(vbase + (j + 2) * UV_PAD);
                unsigned long long v3 = *(const unsigned long long*)(vbase + (j + 3) * UV_PAD);
                addabs2(aA, tA, v0, mask); addabs2(aB, tB, v0, mask);
                addabs2(aA, tA, v1, mask); addabs2(aB, tB, v1, mask);
                addabs2(aA, tA, v2, mask); addabs2(aB, tB, v2, mask);
                addabs2(aA, tA, v3, mask); addabs2(aB, tB, v3, mask);
            }
        }

        unsigned long long s2 = padd2(aA, aB);
        float sx = lo2(s2), sy = hi2(s2);
        // reduce over isub lanes (xor 8, 16)
        sx += __shfl_xor_sync(0xffffffffu, sx, 8);
        sx += __shfl_xor_sync(0xffffffffu, sx, 16);
        sy += __shfl_xor_sync(0xffffffffu, sy, 8);
        sy += __shfl_xor_sync(0xffffffffu, sy, 16);
        if (lane < 8) red[w * 8 + hp] = make_float2(sx, sy);
    }
    __syncthreads();

    // ================= combine: S[b][h] =================
    if (tid < 16) {
        int h  = tid;
        int hp = h >> 1;
        int c  = h & 1;
        float sabs = 0.0f;
#pragma unroll
        for (int ww = 0; ww < 16; ++ww) {
            float2 r = red[ww * 8 + hp];
            sabs += c ? r.y : r.x;
        }
        float lin = (lr[h * 4 + 0] + lr[h * 4 + 1]) + (lr[h * 4 + 2] + lr[h * 4 + 3]);
        lin += cs[h] * (float)R_PAIRS;
        g_S[b * HID_ + hbase + h] = 0.5f * (lin + sabs);
    }
}

// ===========================================================================
// Out kernel: out[b][o] = W2[o,:].S[b,:] + R*b2[o]. grid = 16, block = 128.
// ===========================================================================
__global__ __launch_bounds__(128) void out_kernel(
    const float* __restrict__ W2, const float* __restrict__ b2,
    float* __restrict__ out)
{
    __shared__ float Ss[HID_];
    const int b   = blockIdx.x;
    const int tid = threadIdx.x;

    Ss[tid] = g_S[b * HID_ + tid];
    __syncthreads();

    if (tid < OUT_) {
        int o = tid;
        const float4* wv = (const float4*)(W2 + o * HID_);
        const float4* sv = (const float4*)Ss;
        float acc = 0.0f;
#pragma unroll
        for (int q2 = 0; q2 < HID_ / 4; ++q2) {
            float4 ww = wv[q2]; float4 ssv = sv[q2];
            acc += ww.x * ssv.x + ww.y * ssv.y + ww.z * ssv.z + ww.w * ssv.w;
        }
        out[b * OUT_ + o] = acc + (float)R_PAIRS * b2[o];
    }
}

// ---------------------------------------------------------------------------
extern "C" void kernel_launch(void* const* d_in, const int* in_sizes, int n_in,
                              void* d_out, int out_size) {
    const float* x   = (const float*)d_in[0];
    const float* emb = (const float*)d_in[1];
    const float* W1  = (const float*)d_in[2];
    const float* b1  = (const float*)d_in[3];
    const float* W2  = (const float*)d_in[4];
    const float* b2  = (const float*)d_in[5];
    float* out = (float*)d_out;

    cudaFuncSetAttribute(fused_kernel,
                         cudaFuncAttributeMaxDynamicSharedMemorySize, SMEM_TOT);
    fused_kernel<<<128, 512, SMEM_TOT>>>(x, emb, W1, b1);
    out_kernel<<<B_, HID_>>>(W2, b2, out);
}

// round 12
// speedup vs baseline: 1.6250x; 1.0208x over previous
#include <cuda_runtime.h>

#define B_      16
#define D_      64
#define N_      256
#define E_      64
#define HID_    128
#define OUT_    64
#define IN_     192
#define R_PAIRS 32640
#define UV_PAD  18

// Cross-block scratch: S[b][h] + per-batch completion counters (zero-init,
// reset to 0 by the consuming block each run -> deterministic across replays)
__device__ float    g_S[B_ * HID_];
__device__ unsigned g_done[B_];

// ---- dynamic smem layout (bytes) ----
#define OFF_XS   0                       // 64*256 floats   = 65536
#define OFF_WT   65536                   // 2048 ull        = 16384
#define OFF_US   81920                   // 256*18 floats   = 18432
#define OFF_VS   100352                  // 256*18 floats   = 18432
#define OFF_CS   118784                  // 16 floats       = 64
#define OFF_LIN  118848                  // 64 floats       = 256
#define OFF_RED  119104                  // 16*8 float2     = 1024
#define SMEM_TOT 120128

// ---------------- packed f32x2 helpers ----------------
__device__ __forceinline__ void fma2(unsigned long long& acc,
                                     unsigned long long w, unsigned long long x) {
    asm("fma.rn.f32x2 %0, %1, %2, %3;" : "=l"(acc) : "l"(w), "l"(x), "l"(acc));
}
__device__ __forceinline__ unsigned long long pack2(float a, float b) {
    unsigned long long r;
    asm("mov.b64 %0, {%1, %2};" : "=l"(r) : "f"(a), "f"(b));
    return r;
}
__device__ __forceinline__ float lo2(unsigned long long v) {
    return __uint_as_float((unsigned)(v & 0xffffffffu));
}
__device__ __forceinline__ float hi2(unsigned long long v) {
    return __uint_as_float((unsigned)(v >> 32));
}
__device__ __forceinline__ unsigned long long padd2(unsigned long long a,
                                                    unsigned long long b) {
    unsigned long long r;
    asm("add.rn.f32x2 %0, %1, %2;" : "=l"(r) : "l"(a), "l"(b));
    return r;
}
__device__ __forceinline__ void addabs2(unsigned long long& acc,
                                        unsigned long long t2, unsigned long long v2,
                                        unsigned long long mask) {
    unsigned long long x;
    asm("add.rn.f32x2 %0, %1, %2;" : "=l"(x) : "l"(t2), "l"(v2));
    asm("and.b64 %0, %1, %2;" : "=l"(x) : "l"(x), "l"(mask));
    asm("add.rn.f32x2 %0, %1, %2;" : "=l"(acc) : "l"(acc), "l"(x));
}

// ===========================================================================
// Single fused kernel. grid = 128 = (b:16, hg:8); block = 512 (16 warps).
// Per block: x stage -> U,V in smem -> Sabs+lin -> S[b][16h]; the LAST block
// per b (completion counter) additionally runs the output GEMM.
// ===========================================================================
__global__ __launch_bounds__(512, 1) void fused_kernel(
    const float* __restrict__ x, const float* __restrict__ emb,
    const float* __restrict__ W1, const float* __restrict__ b1,
    const float* __restrict__ W2, const float* __restrict__ b2,
    float* __restrict__ out)
{
    extern __shared__ __align__(16) char smem[];
    float*              xs  = (float*)(smem + OFF_XS);    // [d][256 n]
    unsigned long long* wt  = (unsigned long long*)(smem + OFF_WT); // dup W
    float*              us  = (float*)(smem + OFF_US);    // [256 n][18]
    float*              vs  = (float*)(smem + OFF_VS);
    float*              cs  = (float*)(smem + OFF_CS);    // [16]
    float*              lr  = (float*)(smem + OFF_LIN);   // [16h][4nq]
    float2*             red = (float2*)(smem + OFF_RED);  // [16w][8hp]

    const int bx    = blockIdx.x;
    const int hg    = bx & 7;
    const int b     = bx >> 3;
    const int hbase = hg * 16;
    const int tid   = threadIdx.x;
    const int w     = tid >> 5;
    const int lane  = tid & 31;

    // ---- stage x[b] (64 KB copy) ----
    {
        const float4* xg = (const float4*)(x + b * D_ * N_);
        float4*       xd = (float4*)xs;
#pragma unroll
        for (int i = 0; i < 8; ++i)
            xd[i * 512 + tid] = xg[i * 512 + tid];
    }
    // ---- duplicated W table ----
#pragma unroll
    for (int i = 0; i < 4; ++i) {
        int idx = i * 512 + tid;               // hl*128 + ab*64 + d
        int hl  = idx >> 7;
        int ab  = (idx >> 6) & 1;
        int d   = idx & 63;
        float wv = W1[(hbase + hl) * IN_ + ab * 64 + d];
        wt[idx] = pack2(wv, wv);
    }
    // ---- C for these 16 h ----
    if (tid < 16) {
        int h = hbase + tid;
        const float4* wr = (const float4*)(W1 + h * IN_ + 2 * D_);
        const float4* er = (const float4*)(emb + b * E_);
        float acc = b1[h];
#pragma unroll
        for (int e4 = 0; e4 < E_ / 4; ++e4) {
            float4 ww = wr[e4]; float4 ee = er[e4];
            acc += ww.x * ee.x + ww.y * ee.y + ww.z * ee.z + ww.w * ee.w;
        }
        cs[tid] = acc;
    }
    __syncthreads();

    // ================= Phase A: U,V into smem + lin partials =================
    {
        const int hq = w >> 2;
        const int nq = w & 3;
        const int n0 = nq * 64 + 2 * lane;

        unsigned long long au[4] = {0,0,0,0}, av[4] = {0,0,0,0};
        const float* xpp = xs + n0;
#pragma unroll 4
        for (int d2 = 0; d2 < 32; ++d2) {
            unsigned long long x0 = *(const unsigned long long*)(xpp + (2 * d2)     * N_);
            unsigned long long x1 = *(const unsigned long long*)(xpp + (2 * d2 + 1) * N_);
#pragma unroll
            for (int hl = 0; hl < 4; ++hl) {
                const ulonglong2* wA = (const ulonglong2*)(wt + (hq * 4 + hl) * 128);
                const ulonglong2* wB = (const ulonglong2*)(wt + (hq * 4 + hl) * 128 + 64);
                ulonglong2 A = wA[d2], Bv = wB[d2];
                fma2(au[hl], A.x,  x0); fma2(au[hl], A.y,  x1);
                fma2(av[hl], Bv.x, x0); fma2(av[hl], Bv.y, x1);
            }
        }

        float nf = (float)n0;
        unsigned long long cu = pack2(255.0f - nf, 254.0f - nf);
        unsigned long long cv = pack2(nf, nf + 1.0f);
#pragma unroll
        for (int hl = 0; hl < 4; ++hl) {
            unsigned long long l = 0ull;
            fma2(l, au[hl], cu); fma2(l, av[hl], cv);
            float lin = lo2(l) + hi2(l);
#pragma unroll
            for (int o = 16; o; o >>= 1)
                lin += __shfl_xor_sync(0xffffffffu, lin, o);
            if (lane == 0) lr[(hq * 4 + hl) * 4 + nq] = lin;
        }

#pragma unroll
        for (int hl = 0; hl < 4; ++hl) {
            int h = hq * 4 + hl;
            us[n0 * UV_PAD + h]       = lo2(au[hl]);
            us[(n0 + 1) * UV_PAD + h] = hi2(au[hl]);
            vs[n0 * UV_PAD + h]       = lo2(av[hl]);
            vs[(n0 + 1) * UV_PAD + h] = hi2(av[hl]);
        }
    }
    __syncthreads();

    // ================= Phase B: Sabs over all pairs (tiles {w, 31-w}) ========
    {
        const unsigned long long mask = 0x7FFFFFFF7FFFFFFFull;
        const int hp   = lane & 7;
        const int isub = lane >> 3;

        float2 ccf = *(const float2*)(cs + 2 * hp);
        unsigned long long ccp = pack2(ccf.x, ccf.y);

        unsigned long long aA = 0ull, aB = 0ull;
#pragma unroll
        for (int rep = 0; rep < 2; ++rep) {
            int tile = rep ? (31 - w) : w;
            int i0   = tile * 8;
            int ia   = i0 + 2 * isub;

            unsigned long long ua = *(const unsigned long long*)(us + ia * UV_PAD + 2 * hp);
            unsigned long long ub = *(const unsigned long long*)(us + (ia + 1) * UV_PAD + 2 * hp);
            unsigned long long tA = padd2(ua, ccp);
            unsigned long long tB = padd2(ub, ccp);

#pragma unroll
            for (int jj = 1; jj < 8; ++jj) {
                unsigned long long vj =
                    *(const unsigned long long*)(vs + (i0 + jj) * UV_PAD + 2 * hp);
                if (2 * isub < jj)     addabs2(aA, tA, vj, mask);
                if (2 * isub + 1 < jj) addabs2(aB, tB, vj, mask);
            }

            const float* vbase = vs + 2 * hp;
            for (int j = i0 + 8; j < N_; j += 4) {
                unsigned long long v0 = *(const unsigned long long*)(vbase + (j + 0) * UV_PAD);
                unsigned long long v1 = *(const unsigned long long*)(vbase + (j + 1) * UV_PAD);
                unsigned long long v2 = *(const unsigned long long*)(vbase + (j + 2) * UV_PAD);
                unsigned long long v3 = *(const unsigned long long*)(vbase + (j + 3) * UV_PAD);
                addabs2(aA, tA, v0, mask); addabs2(aB, tB, v0, mask);
                addabs2(aA, tA, v1, mask); addabs2(aB, tB, v1, mask);
                addabs2(aA, tA, v2, mask); addabs2(aB, tB, v2, mask);
                addabs2(aA, tA, v3, mask); addabs2(aB, tB, v3, mask);
            }
        }

        unsigned long long s2 = padd2(aA, aB);
        float sx = lo2(s2), sy = hi2(s2);
        sx += __shfl_xor_sync(0xffffffffu, sx, 8);
        sx += __shfl_xor_sync(0xffffffffu, sx, 16);
        sy += __shfl_xor_sync(0xffffffffu, sy, 8);
        sy += __shfl_xor_sync(0xffffffffu, sy, 16);
        if (lane < 8) red[w * 8 + hp] = make_float2(sx, sy);
    }
    __syncthreads();

    // ================= combine: S[b][16h] =================
    if (tid < 16) {
        int h  = tid;
        int hp = h >> 1;
        int c  = h & 1;
        float sabs = 0.0f;
#pragma unroll
        for (int ww = 0; ww < 16; ++ww) {
            float2 r = red[ww * 8 + hp];
            sabs += c ? r.y : r.x;
        }
        float lin = (lr[h * 4 + 0] + lr[h * 4 + 1]) + (lr[h * 4 + 2] + lr[h * 4 + 3]);
        lin += cs[h] * (float)R_PAIRS;
        g_S[b * HID_ + hbase + h] = 0.5f * (lin + sabs);
    }

    // ================= completion: last block per b does the out GEMM ========
    __shared__ unsigned last_flag;
    __syncthreads();              // S writes (tid<16) issued before the fence below
    if (tid == 0) {
        __threadfence();          // publish g_S[b][hbase..]
        unsigned v = atomicAdd(&g_done[b], 1u);
        last_flag = (v == 7u);
        if (v == 7u) {
            g_done[b] = 0;        // reset for next graph replay (deterministic)
            __threadfence();      // acquire: other blocks' g_S writes now visible
        }
    }
    __syncthreads();

    if (last_flag) {
        float* Ss = xs;           // reuse dynamic smem (xs region is dead now)
        if (tid < HID_) Ss[tid] = g_S[b * HID_ + tid];
        __syncthreads();

        // 512 threads: o = tid>>3 (64 outputs), 8 lanes each over 16 h
        int o   = tid >> 3;
        int sub = tid & 7;
        const float4* wv = (const float4*)(W2 + o * HID_ + sub * 16);
        const float4* sv = (const float4*)(Ss + sub * 16);
        float acc = 0.0f;
#pragma unroll
        for (int q2 = 0; q2 < 4; ++q2) {
            float4 ww = wv[q2]; float4 ssv = sv[q2];
            acc += ww.x * ssv.x + ww.y * ssv.y + ww.z * ssv.z + ww.w * ssv.w;
        }
#pragma unroll
        for (int off = 4; off; off >>= 1)
            acc += __shfl_xor_sync(0xffffffffu, acc, off);
        if (sub == 0)
            out[b * OUT_ + o] = acc + (float)R_PAIRS * b2[o];
    }
}

// ---------------------------------------------------------------------------
extern "C" void kernel_launch(void* const* d_in, const int* in_sizes, int n_in,
                              void* d_out, int out_size) {
    const float* x   = (const float*)d_in[0];
    const float* emb = (const float*)d_in[1];
    const float* W1  = (const float*)d_in[2];
    const float* b1  = (const float*)d_in[3];
    const float* W2  = (const float*)d_in[4];
    const float* b2  = (const float*)d_in[5];
    float* out = (float*)d_out;

    cudaFuncSetAttribute(fused_kernel,
                         cudaFuncAttributeMaxDynamicSharedMemorySize, SMEM_TOT);
    fused_kernel<<<128, 512, SMEM_TOT>>>(x, emb, W1, b1, W2, b2, out);
}